// round 2
// baseline (speedup 1.0000x reference)
#include <cuda_runtime.h>
#include <math.h>

#define Hn   512
#define Bn   1024
#define Vn   1024
#define Tn   64
#define GENn 100

// ---------------- persistent device scratch (no allocs allowed) ----------------
__device__ float d_Wt[Hn * 4 * Hn];    // [512][2048]  W_hh permuted+transposed: Wt[k][p], p=j*4+g
__device__ float d_W1t[Hn * 128];      // [512][128]   W1 transposed, padded 100->128
__device__ float d_W2t[GENn * Vn];     // [100][1024]  W2 transposed
__device__ float d_h[2][Bn * Hn];      // ping-pong hidden state
__device__ float d_c[Bn * Hn];         // cell state (in-place)
__device__ int   d_tok[Bn];            // current token per batch row

// ---------------- weight re-layout (runs every launch; ~10us) ----------------
__global__ void prep_kernel(const float* __restrict__ W_hh,
                            const float* __restrict__ W1,
                            const float* __restrict__ W2) {
    int id = blockIdx.x * blockDim.x + threadIdx.x;
    const int n1 = Hn * 4 * Hn;     // 1048576
    const int n2 = Hn * 128;        // 65536
    const int n3 = GENn * Vn;       // 102400
    if (id < n1) {
        int k = id >> 11, p = id & 2047;
        int j = p >> 2, g = p & 3;
        d_Wt[id] = W_hh[(g * Hn + j) * Hn + k];
    } else if (id < n1 + n2) {
        int i = id - n1;
        int k = i >> 7, j = i & 127;
        d_W1t[i] = (j < GENn) ? W1[j * Hn + k] : 0.0f;
    } else if (id < n1 + n2 + n3) {
        int i = id - n1 - n2;
        int k = i >> 10, v = i & 1023;
        d_W2t[i] = W2[v * GENn + k];
    }
}

// ---------------- h0/c0 expansion + initial token from onehots ----------------
__global__ void init_kernel(const float* __restrict__ input,
                            const float* __restrict__ Wh, const float* __restrict__ bh,
                            const float* __restrict__ Wc, const float* __restrict__ bc,
                            const float* __restrict__ onehots) {
    int id = blockIdx.x * blockDim.x + threadIdx.x;
    if (id < Bn * Hn) {
        int b = id / Hn, j = id % Hn;
        float x = input[b];
        d_h[0][id] = x * Wh[j] + bh[j];
        d_c[id]    = x * Wc[j] + bc[j];
    } else {
        int i2 = id - Bn * Hn;
        if (i2 < Bn * Vn) {
            int b = i2 >> 10, v = i2 & 1023;
            if (onehots[(size_t)b * (Tn * Vn) + v] > 0.5f) d_tok[b] = v;
        }
    }
}

// ---------------- gates GEMM (h @ Whh^T permuted) + fused LSTM cell ----------------
// C[b,p] tile 128x128, K=512. p = j*4+gate so a thread's 8-wide micro-column
// holds 2 complete (i,f,g,o) groups -> cell computed in the epilogue.
__global__ __launch_bounds__(256) void gates_kernel(
    int cur,
    const float* __restrict__ W_ih,
    const float* __restrict__ b_ih,
    const float* __restrict__ b_hh) {
    __shared__ float As[16][128];   // [k][b-row]
    __shared__ float Bs[16][128];   // [k][p]

    const float* hin  = d_h[cur];
    float*       hout = d_h[cur ^ 1];

    int tid = threadIdx.x;
    int tx = tid & 15, ty = tid >> 4;
    int bn0 = blockIdx.x * 128;     // p base
    int bm0 = blockIdx.y * 128;     // b base

    float acc[8][8];
#pragma unroll
    for (int r = 0; r < 8; r++)
#pragma unroll
        for (int q = 0; q < 8; q++) acc[r][q] = 0.0f;

    for (int k0 = 0; k0 < Hn; k0 += 16) {
        // A tile: 128 rows x 16 k, stored transposed into As[k][row]
#pragma unroll
        for (int i = 0; i < 2; i++) {
            int idx = tid + i * 256;        // 512 float4 total
            int row = idx >> 2;
            int c4  = (idx & 3) * 4;
            float4 v = *(const float4*)&hin[(size_t)(bm0 + row) * Hn + k0 + c4];
            As[c4 + 0][row] = v.x; As[c4 + 1][row] = v.y;
            As[c4 + 2][row] = v.z; As[c4 + 3][row] = v.w;
        }
        // B tile: 16 k x 128 p, direct
#pragma unroll
        for (int i = 0; i < 2; i++) {
            int idx = tid + i * 256;        // 512 float4 total
            int row = idx >> 5;
            int c4  = (idx & 31) * 4;
            *(float4*)&Bs[row][c4] = *(const float4*)&d_Wt[(size_t)(k0 + row) * 2048 + bn0 + c4];
        }
        __syncthreads();
#pragma unroll
        for (int kk = 0; kk < 16; kk++) {
            float a[8], bb[8];
            *(float4*)&a[0]  = *(const float4*)&As[kk][ty * 8];
            *(float4*)&a[4]  = *(const float4*)&As[kk][ty * 8 + 4];
            *(float4*)&bb[0] = *(const float4*)&Bs[kk][tx * 8];
            *(float4*)&bb[4] = *(const float4*)&Bs[kk][tx * 8 + 4];
#pragma unroll
            for (int r = 0; r < 8; r++)
#pragma unroll
                for (int q = 0; q < 8; q++) acc[r][q] += a[r] * bb[q];
        }
        __syncthreads();
    }

    // epilogue: + W_ih[:,tok] + bias, LSTM cell, write h/c
    int p0 = bn0 + tx * 8;
    int j0 = p0 >> 2;                       // covers j0, j0+1
    float bias[2][4];
#pragma unroll
    for (int jj = 0; jj < 2; jj++)
#pragma unroll
        for (int g = 0; g < 4; g++) {
            int row = g * Hn + (j0 + jj);
            bias[jj][g] = b_ih[row] + b_hh[row];
        }

#pragma unroll
    for (int r = 0; r < 8; r++) {
        int b_idx = bm0 + ty * 8 + r;
        int tk = d_tok[b_idx];
#pragma unroll
        for (int jj = 0; jj < 2; jj++) {
            int j = j0 + jj;
            float gi = acc[r][jj * 4 + 0] + W_ih[(size_t)(0 * Hn + j) * Vn + tk] + bias[jj][0];
            float gf = acc[r][jj * 4 + 1] + W_ih[(size_t)(1 * Hn + j) * Vn + tk] + bias[jj][1];
            float gg = acc[r][jj * 4 + 2] + W_ih[(size_t)(2 * Hn + j) * Vn + tk] + bias[jj][2];
            float go = acc[r][jj * 4 + 3] + W_ih[(size_t)(3 * Hn + j) * Vn + tk] + bias[jj][3];
            float si = 1.0f / (1.0f + expf(-gi));
            float sf = 1.0f / (1.0f + expf(-gf));
            float so = 1.0f / (1.0f + expf(-go));
            float tg = tanhf(gg);
            int   ci = b_idx * Hn + j;
            float cn = sf * d_c[ci] + si * tg;
            d_c[ci]  = cn;
            hout[ci] = so * tanhf(cn);
        }
    }
}

// ---------------- head: z = relu(h@W1^T+b1); logits = z@W2^T+b2; log_softmax; argmax ----------------
// One CTA = 8 batch rows x full vocab. 8 warps. Warp w computes z-row w, then
// logits for ALL 8 rows over its two 64-wide v-chunks (register reuse across rows
// -> W2t read exactly once per CTA).
__global__ __launch_bounds__(256) void head_kernel(
    int nxt,
    const float* __restrict__ b1,
    const float* __restrict__ b2,
    float* __restrict__ out) {
    __shared__ float sbuf[8192];            // hs[8][512] @0 ; w1s[32][128] @4096
    __shared__ float zs[8][100];
    __shared__ float red[8][8];
    __shared__ int   redi[8][8];

    const float* h = d_h[nxt];
    int tid = threadIdx.x;
    int w = tid >> 5, l = tid & 31;
    int b0 = blockIdx.x * 8;

    float* hs  = sbuf;
    float* w1s = sbuf + 4096;

    // load 8 h rows
    {
        const float4* src = (const float4*)(h + (size_t)b0 * Hn);
#pragma unroll
        for (int i = 0; i < 4; i++) ((float4*)hs)[tid + i * 256] = src[tid + i * 256];
    }

    // ---- z phase: warp w -> row w; 4 j per lane; W1t staged in 32-k chunks ----
    float za[4] = {0.f, 0.f, 0.f, 0.f};
    for (int c0 = 0; c0 < Hn; c0 += 32) {
        __syncthreads();
        const float4* src = (const float4*)(d_W1t + c0 * 128);
#pragma unroll
        for (int i = 0; i < 4; i++) ((float4*)w1s)[tid + i * 256] = src[tid + i * 256];
        __syncthreads();
#pragma unroll
        for (int kk = 0; kk < 32; kk++) {
            float hv = hs[w * Hn + c0 + kk];
#pragma unroll
            for (int s = 0; s < 4; s++) za[s] += hv * w1s[kk * 128 + l + s * 32];
        }
    }
    __syncthreads();
#pragma unroll
    for (int s = 0; s < 4; s++) {
        int j = l + s * 32;
        if (j < GENn) zs[w][j] = fmaxf(za[s] + b1[j], 0.0f);
    }
    __syncthreads();

    // ---- logits: warp w covers v-chunks {w, w+8} (64 v each), all 8 rows ----
    float lg[2][2][8];
#pragma unroll
    for (int cc = 0; cc < 2; cc++)
#pragma unroll
        for (int hh = 0; hh < 2; hh++)
#pragma unroll
            for (int r = 0; r < 8; r++) lg[cc][hh][r] = 0.0f;

#pragma unroll
    for (int cc = 0; cc < 2; cc++) {
        int v0 = (w + cc * 8) * 64;
        for (int k = 0; k < GENn; k++) {
            float w2a = d_W2t[k * Vn + v0 + l];
            float w2b = d_W2t[k * Vn + v0 + 32 + l];
#pragma unroll
            for (int r = 0; r < 8; r++) {
                float zv = zs[r][k];
                lg[cc][0][r] += w2a * zv;
                lg[cc][1][r] += w2b * zv;
            }
        }
        float ba = b2[v0 + l], bb2 = b2[v0 + 32 + l];
#pragma unroll
        for (int r = 0; r < 8; r++) { lg[cc][0][r] += ba; lg[cc][1][r] += bb2; }
    }

    // ---- per-row max + argmax (warp-local, then cross-warp via smem) ----
#pragma unroll
    for (int r = 0; r < 8; r++) {
        float m = -INFINITY; int a = 0x7fffffff;
#pragma unroll
        for (int cc = 0; cc < 2; cc++)
#pragma unroll
            for (int hh = 0; hh < 2; hh++) {
                float val = lg[cc][hh][r];
                int vv = (w + cc * 8) * 64 + hh * 32 + l;
                if (val > m || (val == m && vv < a)) { m = val; a = vv; }
            }
#pragma unroll
        for (int o = 16; o > 0; o >>= 1) {
            float m2 = __shfl_xor_sync(0xffffffffu, m, o);
            int   a2 = __shfl_xor_sync(0xffffffffu, a, o);
            if (m2 > m || (m2 == m && a2 < a)) { m = m2; a = a2; }
        }
        if (l == 0) { red[r][w] = m; redi[r][w] = a; }
    }
    __syncthreads();

    float gmax[8];
#pragma unroll
    for (int r = 0; r < 8; r++) {
        float m = red[r][0];
#pragma unroll
        for (int ww = 1; ww < 8; ww++) m = fmaxf(m, red[r][ww]);
        gmax[r] = m;
    }
    if (tid < 8) {   // global argmax, first-occurrence tie-break
        float m = red[tid][0]; int a = redi[tid][0];
        for (int ww = 1; ww < 8; ww++) {
            float m2 = red[tid][ww]; int a2 = redi[tid][ww];
            if (m2 > m || (m2 == m && a2 < a)) { m = m2; a = a2; }
        }
        d_tok[b0 + tid] = a;
    }
    __syncthreads();

    // ---- per-row sum(exp(x - max)) ----
    float rsum[8];
#pragma unroll
    for (int r = 0; r < 8; r++) rsum[r] = 0.0f;
#pragma unroll
    for (int cc = 0; cc < 2; cc++)
#pragma unroll
        for (int hh = 0; hh < 2; hh++)
#pragma unroll
            for (int r = 0; r < 8; r++) rsum[r] += expf(lg[cc][hh][r] - gmax[r]);
#pragma unroll
    for (int r = 0; r < 8; r++) {
#pragma unroll
        for (int o = 16; o > 0; o >>= 1) rsum[r] += __shfl_xor_sync(0xffffffffu, rsum[r], o);
        if (l == 0) red[r][w] = rsum[r];
    }
    __syncthreads();

    float logZ[8];
#pragma unroll
    for (int r = 0; r < 8; r++) {
        float s = 0.0f;
#pragma unroll
        for (int ww = 0; ww < 8; ww++) s += red[r][ww];
        logZ[r] = logf(s);
    }

    // ---- write logp ----
#pragma unroll
    for (int cc = 0; cc < 2; cc++)
#pragma unroll
        for (int hh = 0; hh < 2; hh++) {
            int v = (w + cc * 8) * 64 + hh * 32 + l;
#pragma unroll
            for (int r = 0; r < 8; r++)
                out[(size_t)(b0 + r) * Vn + v] = lg[cc][hh][r] - gmax[r] - logZ[r];
        }
}

// ---------------- launch ----------------
extern "C" void kernel_launch(void* const* d_in, const int* in_sizes, int n_in,
                              void* d_out, int out_size) {
    (void)out_size;
    // input order: input, onehots, digits, [teacher], Wh, bh, Wc, bc,
    //              W_ih, W_hh, b_ih, b_hh, W1, b1, W2, b2
    int off = (n_in >= 16 && in_sizes[3] == 1) ? 4 : 3;  // teacher scalar present?
    const float* input   = (const float*)d_in[0];
    const float* onehots = (const float*)d_in[1];
    const float* Wh   = (const float*)d_in[off + 0];
    const float* bh   = (const float*)d_in[off + 1];
    const float* Wc   = (const float*)d_in[off + 2];
    const float* bc   = (const float*)d_in[off + 3];
    const float* W_ih = (const float*)d_in[off + 4];
    const float* W_hh = (const float*)d_in[off + 5];
    const float* b_ih = (const float*)d_in[off + 6];
    const float* b_hh = (const float*)d_in[off + 7];
    const float* W1   = (const float*)d_in[off + 8];
    const float* b1   = (const float*)d_in[off + 9];
    const float* W2   = (const float*)d_in[off + 10];
    const float* b2   = (const float*)d_in[off + 11];
    float* out = (float*)d_out;

    const int prepN = Hn * 4 * Hn + Hn * 128 + GENn * Vn;
    prep_kernel<<<(prepN + 255) / 256, 256>>>(W_hh, W1, W2);

    const int initN = Bn * Hn + Bn * Vn;
    init_kernel<<<(initN + 255) / 256, 256>>>(input, Wh, bh, Wc, bc, onehots);

    for (int t = 0; t < Tn; t++) {
        int cur = t & 1;
        gates_kernel<<<dim3(16, 8), 256>>>(cur, W_ih, b_ih, b_hh);
        head_kernel<<<128, 256>>>(cur ^ 1, b1, b2, out + (size_t)t * Bn * Vn);
    }
}

// round 3
// speedup vs baseline: 1.0250x; 1.0250x over previous
#include <cuda_runtime.h>
#include <math.h>

#define Hn   512
#define Bn   1024
#define Vn   1024
#define Tn   64
#define GENn 100
#define GPAD 104            // GEN padded for unroll
#define W2ROWS 108          // GEN padded + prefetch slack (rows 100..107 zeroed)

// ---------------- persistent device scratch (no allocs allowed) ----------------
__device__ float d_Wt[Hn * 4 * Hn];         // [512][2048]  W_hh permuted+transposed
__device__ float d_W1t[(Hn + 1) * 128];     // [513][128]   W1^T padded (row 512 = prefetch slack)
__device__ float d_W2t[W2ROWS * Vn];        // [108][1024]  W2^T padded
__device__ float d_h[2][Bn * Hn];           // ping-pong hidden state
__device__ float d_c[Bn * Hn];              // cell state
__device__ int   d_tok[Bn];                 // current token per batch row

// ---------------- weight re-layout ----------------
__global__ void prep_kernel(const float* __restrict__ W_hh,
                            const float* __restrict__ W1,
                            const float* __restrict__ W2) {
    int id = blockIdx.x * blockDim.x + threadIdx.x;
    const int n1 = Hn * 4 * Hn;             // 1048576
    const int n2 = (Hn + 1) * 128;          // 65664
    const int n3 = W2ROWS * Vn;             // 110592
    if (id < n1) {
        int k = id >> 11, p = id & 2047;
        int j = p >> 2, g = p & 3;
        d_Wt[id] = W_hh[(g * Hn + j) * Hn + k];
    } else if (id < n1 + n2) {
        int i = id - n1;
        int k = i >> 7, j = i & 127;
        d_W1t[i] = (j < GENn && k < Hn) ? W1[j * Hn + k] : 0.0f;
    } else if (id < n1 + n2 + n3) {
        int i = id - n1 - n2;
        int k = i >> 10, v = i & 1023;
        d_W2t[i] = (k < GENn) ? W2[v * GENn + k] : 0.0f;
    }
}

// ---------------- h0/c0 expansion + initial token ----------------
__global__ void init_kernel(const float* __restrict__ input,
                            const float* __restrict__ Wh, const float* __restrict__ bh,
                            const float* __restrict__ Wc, const float* __restrict__ bc,
                            const float* __restrict__ onehots) {
    int id = blockIdx.x * blockDim.x + threadIdx.x;
    if (id < Bn * Hn) {
        int b = id / Hn, j = id % Hn;
        float x = input[b];
        d_h[0][id] = x * Wh[j] + bh[j];
        d_c[id]    = x * Wc[j] + bc[j];
    } else {
        int i2 = id - Bn * Hn;
        if (i2 < Bn * Vn) {
            int b = i2 >> 10, v = i2 & 1023;
            if (onehots[(size_t)b * (Tn * Vn) + v] > 0.5f) d_tok[b] = v;
        }
    }
}

// ---------------- gates GEMM + fused LSTM cell (unchanged; near FFMA roofline) ----------------
__global__ __launch_bounds__(256) void gates_kernel(
    int cur,
    const float* __restrict__ W_ih,
    const float* __restrict__ b_ih,
    const float* __restrict__ b_hh) {
    __shared__ float As[16][128];
    __shared__ float Bs[16][128];

    const float* hin  = d_h[cur];
    float*       hout = d_h[cur ^ 1];

    int tid = threadIdx.x;
    int tx = tid & 15, ty = tid >> 4;
    int bn0 = blockIdx.x * 128;
    int bm0 = blockIdx.y * 128;

    float acc[8][8];
#pragma unroll
    for (int r = 0; r < 8; r++)
#pragma unroll
        for (int q = 0; q < 8; q++) acc[r][q] = 0.0f;

    for (int k0 = 0; k0 < Hn; k0 += 16) {
#pragma unroll
        for (int i = 0; i < 2; i++) {
            int idx = tid + i * 256;
            int row = idx >> 2;
            int c4  = (idx & 3) * 4;
            float4 v = *(const float4*)&hin[(size_t)(bm0 + row) * Hn + k0 + c4];
            As[c4 + 0][row] = v.x; As[c4 + 1][row] = v.y;
            As[c4 + 2][row] = v.z; As[c4 + 3][row] = v.w;
        }
#pragma unroll
        for (int i = 0; i < 2; i++) {
            int idx = tid + i * 256;
            int row = idx >> 5;
            int c4  = (idx & 31) * 4;
            *(float4*)&Bs[row][c4] = *(const float4*)&d_Wt[(size_t)(k0 + row) * 2048 + bn0 + c4];
        }
        __syncthreads();
#pragma unroll
        for (int kk = 0; kk < 16; kk++) {
            float a[8], bb[8];
            *(float4*)&a[0]  = *(const float4*)&As[kk][ty * 8];
            *(float4*)&a[4]  = *(const float4*)&As[kk][ty * 8 + 4];
            *(float4*)&bb[0] = *(const float4*)&Bs[kk][tx * 8];
            *(float4*)&bb[4] = *(const float4*)&Bs[kk][tx * 8 + 4];
#pragma unroll
            for (int r = 0; r < 8; r++)
#pragma unroll
                for (int q = 0; q < 8; q++) acc[r][q] += a[r] * bb[q];
        }
        __syncthreads();
    }

    int p0 = bn0 + tx * 8;
    int j0 = p0 >> 2;
    float bias[2][4];
#pragma unroll
    for (int jj = 0; jj < 2; jj++)
#pragma unroll
        for (int g = 0; g < 4; g++) {
            int row = g * Hn + (j0 + jj);
            bias[jj][g] = b_ih[row] + b_hh[row];
        }

#pragma unroll
    for (int r = 0; r < 8; r++) {
        int b_idx = bm0 + ty * 8 + r;
        int tk = d_tok[b_idx];
#pragma unroll
        for (int jj = 0; jj < 2; jj++) {
            int j = j0 + jj;
            float gi = acc[r][jj * 4 + 0] + W_ih[(size_t)(0 * Hn + j) * Vn + tk] + bias[jj][0];
            float gf = acc[r][jj * 4 + 1] + W_ih[(size_t)(1 * Hn + j) * Vn + tk] + bias[jj][1];
            float gg = acc[r][jj * 4 + 2] + W_ih[(size_t)(2 * Hn + j) * Vn + tk] + bias[jj][2];
            float go = acc[r][jj * 4 + 3] + W_ih[(size_t)(3 * Hn + j) * Vn + tk] + bias[jj][3];
            float si = 1.0f / (1.0f + expf(-gi));
            float sf = 1.0f / (1.0f + expf(-gf));
            float so = 1.0f / (1.0f + expf(-go));
            float tg = tanhf(gg);
            int   ci = b_idx * Hn + j;
            float cn = sf * d_c[ci] + si * tg;
            d_c[ci]  = cn;
            hout[ci] = so * tanhf(cn);
        }
    }
}

// ---------------- head v2: 512 threads, 16 warps, 8 rows/CTA ----------------
// z phase:  warp w -> row (w&7), k-half (w>>3); direct LDG.128 of W1t, prefetch 1.
// logits:   warp w -> 64 vocab cols [w*64, w*64+64) as float2; z kept k-major
//           in smem so 8 rows come from 2 broadcast LDS.128; 4-deep LDG pipeline.
__global__ __launch_bounds__(512) void head_kernel(
    int nxt,
    const float* __restrict__ b1,
    const float* __restrict__ b2,
    float* __restrict__ out) {
    __shared__ float hs[8][512];        // 16KB
    __shared__ float zpart[16][128];    // 8KB
    __shared__ float zs[GPAD][8];       // k-major z, 3.3KB
    __shared__ float red[8][16];
    __shared__ int   redi[8][16];
    __shared__ float gmaxS[8];

    const float* __restrict__ h = d_h[nxt];
    int tid = threadIdx.x;
    int w = tid >> 5, l = tid & 31;
    int b0 = blockIdx.x * 8;

    // load 8 h rows (1024 float4, 2 per thread)
    {
        const float4* src = (const float4*)(h + (size_t)b0 * Hn);
        float4* dst = (float4*)hs;
        dst[tid]       = src[tid];
        dst[tid + 512] = src[tid + 512];
    }
    __syncthreads();

    // ---- z partials ----
    {
        int r  = w & 7;
        int kh = w >> 3;
        const float4* w1p = (const float4*)d_W1t + kh * 256 * 32 + l;
        const float*  hrow = hs[r] + kh * 256;
        float4 acc = make_float4(0.f, 0.f, 0.f, 0.f);
        float4 cur = w1p[0];
#pragma unroll 8
        for (int k = 0; k < 256; k++) {
            float4 nv = w1p[(k + 1) * 32];   // row 512 pad makes last read safe
            float hv = hrow[k];
            acc.x += hv * cur.x; acc.y += hv * cur.y;
            acc.z += hv * cur.z; acc.w += hv * cur.w;
            cur = nv;
        }
        *(float4*)&zpart[w][4 * l] = acc;
    }
    __syncthreads();

    // combine halves + bias + relu; transpose to zs[k][r]
    for (int idx = tid; idx < 8 * 128; idx += 512) {
        int r = idx >> 7, j = idx & 127;
        if (j < GPAD) {
            float v = 0.0f;
            if (j < GENn)
                v = fmaxf(zpart[r][j] + zpart[r + 8][j] + b1[j], 0.0f);
            zs[j][r] = v;
        }
    }
    __syncthreads();

    // ---- logits: 16 accumulators (8 rows x float2) ----
    float lg0[8], lg1[8];
#pragma unroll
    for (int r = 0; r < 8; r++) { lg0[r] = 0.f; lg1[r] = 0.f; }
    {
        const float2* w2p = (const float2*)d_W2t + w * 32 + l;  // element k: w2p[k*512]
        float2 buf[4];
#pragma unroll
        for (int i = 0; i < 4; i++) buf[i] = w2p[i * 512];
        for (int k0 = 0; k0 < GPAD; k0 += 4) {
            float2 nbuf[4];
#pragma unroll
            for (int i = 0; i < 4; i++) nbuf[i] = w2p[(k0 + 4 + i) * 512];  // rows <108, padded
#pragma unroll
            for (int i = 0; i < 4; i++) {
                int k = k0 + i;
                float zv[8];
                *(float4*)&zv[0] = *(const float4*)&zs[k][0];
                *(float4*)&zv[4] = *(const float4*)&zs[k][4];
#pragma unroll
                for (int r = 0; r < 8; r++) {
                    lg0[r] += buf[i].x * zv[r];
                    lg1[r] += buf[i].y * zv[r];
                }
            }
#pragma unroll
            for (int i = 0; i < 4; i++) buf[i] = nbuf[i];
        }
        float bx = b2[w * 64 + 2 * l], by = b2[w * 64 + 2 * l + 1];
#pragma unroll
        for (int r = 0; r < 8; r++) { lg0[r] += bx; lg1[r] += by; }
    }

    // ---- per-row max + argmax ----
    int vbase = w * 64 + 2 * l;
#pragma unroll
    for (int r = 0; r < 8; r++) {
        float m; int a;
        if (lg1[r] > lg0[r]) { m = lg1[r]; a = vbase + 1; }
        else                 { m = lg0[r]; a = vbase;     }
#pragma unroll
        for (int o = 16; o > 0; o >>= 1) {
            float m2 = __shfl_xor_sync(0xffffffffu, m, o);
            int   a2 = __shfl_xor_sync(0xffffffffu, a, o);
            if (m2 > m || (m2 == m && a2 < a)) { m = m2; a = a2; }
        }
        if (l == 0) { red[r][w] = m; redi[r][w] = a; }
    }
    __syncthreads();

    if (tid < 8) {   // final max+argmax, first-occurrence tie-break
        float m = red[tid][0]; int a = redi[tid][0];
#pragma unroll
        for (int ww = 1; ww < 16; ww++) {
            float m2 = red[tid][ww]; int a2 = redi[tid][ww];
            if (m2 > m || (m2 == m && a2 < a)) { m = m2; a = a2; }
        }
        d_tok[b0 + tid] = a;
        gmaxS[tid] = m;
    }
    __syncthreads();

    float gmax[8];
#pragma unroll
    for (int r = 0; r < 8; r++) gmax[r] = gmaxS[r];

    // ---- per-row sum(exp(x - max)) ----
#pragma unroll
    for (int r = 0; r < 8; r++) {
        float s = expf(lg0[r] - gmax[r]) + expf(lg1[r] - gmax[r]);
#pragma unroll
        for (int o = 16; o > 0; o >>= 1) s += __shfl_xor_sync(0xffffffffu, s, o);
        if (l == 0) red[r][w] = s;
    }
    __syncthreads();

    float logZ[8];
#pragma unroll
    for (int r = 0; r < 8; r++) {
        float s = 0.0f;
#pragma unroll
        for (int ww = 0; ww < 16; ww++) s += red[r][ww];
        logZ[r] = logf(s);
    }

    // ---- write logp (float2 per row per lane) ----
#pragma unroll
    for (int r = 0; r < 8; r++) {
        float2 o2;
        o2.x = lg0[r] - gmax[r] - logZ[r];
        o2.y = lg1[r] - gmax[r] - logZ[r];
        *(float2*)&out[(size_t)(b0 + r) * Vn + vbase] = o2;
    }
}

// ---------------- launch ----------------
extern "C" void kernel_launch(void* const* d_in, const int* in_sizes, int n_in,
                              void* d_out, int out_size) {
    (void)out_size;
    int off = (n_in >= 16 && in_sizes[3] == 1) ? 4 : 3;
    const float* input   = (const float*)d_in[0];
    const float* onehots = (const float*)d_in[1];
    const float* Wh   = (const float*)d_in[off + 0];
    const float* bh   = (const float*)d_in[off + 1];
    const float* Wc   = (const float*)d_in[off + 2];
    const float* bc   = (const float*)d_in[off + 3];
    const float* W_ih = (const float*)d_in[off + 4];
    const float* W_hh = (const float*)d_in[off + 5];
    const float* b_ih = (const float*)d_in[off + 6];
    const float* b_hh = (const float*)d_in[off + 7];
    const float* W1   = (const float*)d_in[off + 8];
    const float* b1   = (const float*)d_in[off + 9];
    const float* W2   = (const float*)d_in[off + 10];
    const float* b2   = (const float*)d_in[off + 11];
    float* out = (float*)d_out;

    const int prepN = Hn * 4 * Hn + (Hn + 1) * 128 + W2ROWS * Vn;
    prep_kernel<<<(prepN + 255) / 256, 256>>>(W_hh, W1, W2);

    const int initN = Bn * Hn + Bn * Vn;
    init_kernel<<<(initN + 255) / 256, 256>>>(input, Wh, bh, Wc, bc, onehots);

    for (int t = 0; t < Tn; t++) {
        int cur = t & 1;
        gates_kernel<<<dim3(16, 8), 256>>>(cur, W_ih, b_ih, b_hh);
        head_kernel<<<128, 512>>>(cur ^ 1, b1, b2, out + (size_t)t * Bn * Vn);
    }
}

// round 8
// speedup vs baseline: 1.1115x; 1.0844x over previous
#include <cuda_runtime.h>
#include <math.h>

#define Hn   512
#define Bn   1024
#define Vn   1024
#define Tn   64
#define GENn 100
#define GPAD 104            // GEN padded for unroll (rows 100..103 zero)
#define W1ROWS (Hn + 8)     // 520: 8 pad rows so z-phase ring prefetch never OOB
#define W2ROWS 112          // GEN padded + 2-block prefetch slack (rows 100..111 zero)

// ---------------- persistent device scratch (no allocs allowed) ----------------
__device__ float d_Wt[Hn * 4 * Hn];         // [512][2048]  W_hh permuted+transposed
__device__ float d_W1t[W1ROWS * 128];       // [520][128]   W1^T padded
__device__ float d_W2t[W2ROWS * Vn];        // [112][1024]  W2^T padded
__device__ float d_h[2][Bn * Hn];           // ping-pong hidden state
__device__ float d_c[Bn * Hn];              // cell state
__device__ int   d_tok[Bn];                 // current token per batch row

// ---------------- weight re-layout ----------------
__global__ void prep_kernel(const float* __restrict__ W_hh,
                            const float* __restrict__ W1,
                            const float* __restrict__ W2) {
    int id = blockIdx.x * blockDim.x + threadIdx.x;
    const int n1 = Hn * 4 * Hn;             // 1048576
    const int n2 = W1ROWS * 128;            // 66560
    const int n3 = W2ROWS * Vn;             // 114688
    if (id < n1) {
        int k = id >> 11, p = id & 2047;
        int j = p >> 2, g = p & 3;
        d_Wt[id] = W_hh[(g * Hn + j) * Hn + k];
    } else if (id < n1 + n2) {
        int i = id - n1;
        int k = i >> 7, j = i & 127;
        d_W1t[i] = (j < GENn && k < Hn) ? W1[j * Hn + k] : 0.0f;
    } else if (id < n1 + n2 + n3) {
        int i = id - n1 - n2;
        int k = i >> 10, v = i & 1023;
        d_W2t[i] = (k < GENn) ? W2[v * GENn + k] : 0.0f;
    }
}

// ---------------- h0/c0 expansion + initial token ----------------
__global__ void init_kernel(const float* __restrict__ input,
                            const float* __restrict__ Wh, const float* __restrict__ bh,
                            const float* __restrict__ Wc, const float* __restrict__ bc,
                            const float* __restrict__ onehots) {
    int id = blockIdx.x * blockDim.x + threadIdx.x;
    if (id < Bn * Hn) {
        int b = id / Hn, j = id % Hn;
        float x = input[b];
        d_h[0][id] = x * Wh[j] + bh[j];
        d_c[id]    = x * Wc[j] + bc[j];
    } else {
        int i2 = id - Bn * Hn;
        if (i2 < Bn * Vn) {
            int b = i2 >> 10, v = i2 & 1023;
            if (onehots[(size_t)b * (Tn * Vn) + v] > 0.5f) d_tok[b] = v;
        }
    }
}

// ---------------- gates GEMM + fused LSTM cell (at FFMA issue ceiling; unchanged) ----------------
__global__ __launch_bounds__(256) void gates_kernel(
    int cur,
    const float* __restrict__ W_ih,
    const float* __restrict__ b_ih,
    const float* __restrict__ b_hh) {
    __shared__ float As[16][128];
    __shared__ float Bs[16][128];

    const float* hin  = d_h[cur];
    float*       hout = d_h[cur ^ 1];

    int tid = threadIdx.x;
    int tx = tid & 15, ty = tid >> 4;
    int bn0 = blockIdx.x * 128;
    int bm0 = blockIdx.y * 128;

    float acc[8][8];
#pragma unroll
    for (int r = 0; r < 8; r++)
#pragma unroll
        for (int q = 0; q < 8; q++) acc[r][q] = 0.0f;

    for (int k0 = 0; k0 < Hn; k0 += 16) {
#pragma unroll
        for (int i = 0; i < 2; i++) {
            int idx = tid + i * 256;
            int row = idx >> 2;
            int c4  = (idx & 3) * 4;
            float4 v = *(const float4*)&hin[(size_t)(bm0 + row) * Hn + k0 + c4];
            As[c4 + 0][row] = v.x; As[c4 + 1][row] = v.y;
            As[c4 + 2][row] = v.z; As[c4 + 3][row] = v.w;
        }
#pragma unroll
        for (int i = 0; i < 2; i++) {
            int idx = tid + i * 256;
            int row = idx >> 5;
            int c4  = (idx & 31) * 4;
            *(float4*)&Bs[row][c4] = *(const float4*)&d_Wt[(size_t)(k0 + row) * 2048 + bn0 + c4];
        }
        __syncthreads();
#pragma unroll
        for (int kk = 0; kk < 16; kk++) {
            float a[8], bb[8];
            *(float4*)&a[0]  = *(const float4*)&As[kk][ty * 8];
            *(float4*)&a[4]  = *(const float4*)&As[kk][ty * 8 + 4];
            *(float4*)&bb[0] = *(const float4*)&Bs[kk][tx * 8];
            *(float4*)&bb[4] = *(const float4*)&Bs[kk][tx * 8 + 4];
#pragma unroll
            for (int r = 0; r < 8; r++)
#pragma unroll
                for (int q = 0; q < 8; q++) acc[r][q] += a[r] * bb[q];
        }
        __syncthreads();
    }

    int p0 = bn0 + tx * 8;
    int j0 = p0 >> 2;
    float bias[2][4];
#pragma unroll
    for (int jj = 0; jj < 2; jj++)
#pragma unroll
        for (int g = 0; g < 4; g++) {
            int row = g * Hn + (j0 + jj);
            bias[jj][g] = b_ih[row] + b_hh[row];
        }

#pragma unroll
    for (int r = 0; r < 8; r++) {
        int b_idx = bm0 + ty * 8 + r;
        int tk = d_tok[b_idx];
#pragma unroll
        for (int jj = 0; jj < 2; jj++) {
            int j = j0 + jj;
            float gi = acc[r][jj * 4 + 0] + W_ih[(size_t)(0 * Hn + j) * Vn + tk] + bias[jj][0];
            float gf = acc[r][jj * 4 + 1] + W_ih[(size_t)(1 * Hn + j) * Vn + tk] + bias[jj][1];
            float gg = acc[r][jj * 4 + 2] + W_ih[(size_t)(2 * Hn + j) * Vn + tk] + bias[jj][2];
            float go = acc[r][jj * 4 + 3] + W_ih[(size_t)(3 * Hn + j) * Vn + tk] + bias[jj][3];
            float si = 1.0f / (1.0f + expf(-gi));
            float sf = 1.0f / (1.0f + expf(-gf));
            float so = 1.0f / (1.0f + expf(-go));
            float tg = tanhf(gg);
            int   ci = b_idx * Hn + j;
            float cn = sf * d_c[ci] + si * tg;
            d_c[ci]  = cn;
            hout[ci] = so * tanhf(cn);
        }
    }
}

// ---------------- head v3: deep-MLP load pipelines ----------------
// z phase:  warp w -> row (w&7), k-half (w>>3); 8-deep register ring of LDG.128.
// logits:   warp w -> 64 vocab cols as float2; 2-block (8-load) prefetch pipeline.
__global__ __launch_bounds__(512) void head_kernel(
    int nxt,
    const float* __restrict__ b1,
    const float* __restrict__ b2,
    float* __restrict__ out) {
    __shared__ float hs[8][512];        // 16KB
    __shared__ float zpart[16][128];    // 8KB
    __shared__ float zs[GPAD][8];       // k-major z
    __shared__ float red[8][16];
    __shared__ int   redi[8][16];
    __shared__ float gmaxS[8];

    const float* __restrict__ h = d_h[nxt];
    int tid = threadIdx.x;
    int w = tid >> 5, l = tid & 31;
    int b0 = blockIdx.x * 8;

    // load 8 h rows (1024 float4, 2 per thread)
    {
        const float4* src = (const float4*)(h + (size_t)b0 * Hn);
        float4* dst = (float4*)hs;
        dst[tid]       = src[tid];
        dst[tid + 512] = src[tid + 512];
    }
    __syncthreads();

    // ---- z partials: 8-deep LDG ring ----
    {
        int r  = w & 7;
        int kh = w >> 3;
        const float4* w1p = (const float4*)d_W1t + (size_t)kh * 256 * 32 + l;
        const float*  hrow = hs[r] + kh * 256;
        float4 ring[8];
#pragma unroll
        for (int i = 0; i < 8; i++) ring[i] = w1p[(size_t)i * 32];
        float4 acc = make_float4(0.f, 0.f, 0.f, 0.f);
#pragma unroll 8
        for (int k = 0; k < 256; k++) {
            float4 cur = ring[k & 7];
            ring[k & 7] = w1p[(size_t)(k + 8) * 32];   // pad rows 512..519 keep this in-bounds
            float hv = hrow[k];
            acc.x += hv * cur.x; acc.y += hv * cur.y;
            acc.z += hv * cur.z; acc.w += hv * cur.w;
        }
        *(float4*)&zpart[w][4 * l] = acc;
    }
    __syncthreads();

    // combine halves + bias + relu; transpose to zs[k][r]
    for (int idx = tid; idx < 8 * 128; idx += 512) {
        int r = idx >> 7, j = idx & 127;
        if (j < GPAD) {
            float v = 0.0f;
            if (j < GENn)
                v = fmaxf(zpart[r][j] + zpart[r + 8][j] + b1[j], 0.0f);
            zs[j][r] = v;
        }
    }
    __syncthreads();

    // ---- logits: 16 accumulators (8 rows x float2), 2-block prefetch ----
    float lg0[8], lg1[8];
#pragma unroll
    for (int r = 0; r < 8; r++) { lg0[r] = 0.f; lg1[r] = 0.f; }
    {
        const float2* w2p = (const float2*)d_W2t + w * 32 + l;  // element k: w2p[k*512]
        float2 p0[4], p1[4];
#pragma unroll
        for (int i = 0; i < 4; i++) p0[i] = w2p[(size_t)i * 512];
#pragma unroll
        for (int i = 0; i < 4; i++) p1[i] = w2p[(size_t)(4 + i) * 512];
        for (int k0 = 0; k0 < GPAD; k0 += 4) {
            float2 nb[4];
#pragma unroll
            for (int i = 0; i < 4; i++) nb[i] = w2p[(size_t)(k0 + 8 + i) * 512];  // rows <112, padded
#pragma unroll
            for (int i = 0; i < 4; i++) {
                int k = k0 + i;
                float zv[8];
                *(float4*)&zv[0] = *(const float4*)&zs[k][0];
                *(float4*)&zv[4] = *(const float4*)&zs[k][4];
#pragma unroll
                for (int r = 0; r < 8; r++) {
                    lg0[r] += p0[i].x * zv[r];
                    lg1[r] += p0[i].y * zv[r];
                }
            }
#pragma unroll
            for (int i = 0; i < 4; i++) { p0[i] = p1[i]; p1[i] = nb[i]; }
        }
        float bx = b2[w * 64 + 2 * l], by = b2[w * 64 + 2 * l + 1];
#pragma unroll
        for (int r = 0; r < 8; r++) { lg0[r] += bx; lg1[r] += by; }
    }

    // ---- per-row max + argmax ----
    int vbase = w * 64 + 2 * l;
#pragma unroll
    for (int r = 0; r < 8; r++) {
        float m; int a;
        if (lg1[r] > lg0[r]) { m = lg1[r]; a = vbase + 1; }
        else                 { m = lg0[r]; a = vbase;     }
#pragma unroll
        for (int o = 16; o > 0; o >>= 1) {
            float m2 = __shfl_xor_sync(0xffffffffu, m, o);
            int   a2 = __shfl_xor_sync(0xffffffffu, a, o);
            if (m2 > m || (m2 == m && a2 < a)) { m = m2; a = a2; }
        }
        if (l == 0) { red[r][w] = m; redi[r][w] = a; }
    }
    __syncthreads();

    if (tid < 8) {   // final max+argmax, first-occurrence tie-break
        float m = red[tid][0]; int a = redi[tid][0];
#pragma unroll
        for (int ww = 1; ww < 16; ww++) {
            float m2 = red[tid][ww]; int a2 = redi[tid][ww];
            if (m2 > m || (m2 == m && a2 < a)) { m = m2; a = a2; }
        }
        d_tok[b0 + tid] = a;
        gmaxS[tid] = m;
    }
    __syncthreads();

    float gmax[8];
#pragma unroll
    for (int r = 0; r < 8; r++) gmax[r] = gmaxS[r];

    // ---- per-row sum(exp(x - max)) ----
#pragma unroll
    for (int r = 0; r < 8; r++) {
        float s = expf(lg0[r] - gmax[r]) + expf(lg1[r] - gmax[r]);
#pragma unroll
        for (int o = 16; o > 0; o >>= 1) s += __shfl_xor_sync(0xffffffffu, s, o);
        if (l == 0) red[r][w] = s;
    }
    __syncthreads();

    float logZ[8];
#pragma unroll
    for (int r = 0; r < 8; r++) {
        float s = 0.0f;
#pragma unroll
        for (int ww = 0; ww < 16; ww++) s += red[r][ww];
        logZ[r] = logf(s);
    }

    // ---- write logp (float2 per row per lane) ----
#pragma unroll
    for (int r = 0; r < 8; r++) {
        float2 o2;
        o2.x = lg0[r] - gmax[r] - logZ[r];
        o2.y = lg1[r] - gmax[r] - logZ[r];
        *(float2*)&out[(size_t)(b0 + r) * Vn + vbase] = o2;
    }
}

// ---------------- launch ----------------
extern "C" void kernel_launch(void* const* d_in, const int* in_sizes, int n_in,
                              void* d_out, int out_size) {
    (void)out_size;
    int off = (n_in >= 16 && in_sizes[3] == 1) ? 4 : 3;
    const float* input   = (const float*)d_in[0];
    const float* onehots = (const float*)d_in[1];
    const float* Wh   = (const float*)d_in[off + 0];
    const float* bh   = (const float*)d_in[off + 1];
    const float* Wc   = (const float*)d_in[off + 2];
    const float* bc   = (const float*)d_in[off + 3];
    const float* W_ih = (const float*)d_in[off + 4];
    const float* W_hh = (const float*)d_in[off + 5];
    const float* b_ih = (const float*)d_in[off + 6];
    const float* b_hh = (const float*)d_in[off + 7];
    const float* W1   = (const float*)d_in[off + 8];
    const float* b1   = (const float*)d_in[off + 9];
    const float* W2   = (const float*)d_in[off + 10];
    const float* b2   = (const float*)d_in[off + 11];
    float* out = (float*)d_out;

    const int prepN = Hn * 4 * Hn + W1ROWS * 128 + W2ROWS * Vn;
    prep_kernel<<<(prepN + 255) / 256, 256>>>(W_hh, W1, W2);

    const int initN = Bn * Hn + Bn * Vn;
    init_kernel<<<(initN + 255) / 256, 256>>>(input, Wh, bh, Wc, bc, onehots);

    for (int t = 0; t < Tn; t++) {
        int cur = t & 1;
        gates_kernel<<<dim3(16, 8), 256>>>(cur, W_ih, b_ih, b_hh);
        head_kernel<<<128, 512>>>(cur ^ 1, b1, b2, out + (size_t)t * Bn * Vn);
    }
}